// round 16
// baseline (speedup 1.0000x reference)
#include <cuda_runtime.h>
#include <cstdint>
#include <math.h>

// Problem constants (fixed by setup_inputs)
#define BB   256   // batch
#define CTXD 512
#define DOF  6
#define WSZ  300
#define ZD   306   // DOF + WSZ
#define ZDP  308   // padded row stride for g_Aw (16B-aligned rows)
#define PGD  256
#define PWD  512
#define HGD  256
#define HWD  512
#define NL   2
#define MS   20
#define NSTEP (MS - 1)

typedef unsigned long long ull;

// ---------------- scratch (device globals; no runtime allocation) ------------
__device__ __align__(16) float g_Aw[(size_t)PWD * BB * ZDP]; // [o][b][j] pad308 (~161MB)
__device__ __align__(16) float g_Ag[BB * PGD * DOF];         // [b][o][j]
__device__ __align__(16) float g_x0[BB * PGD];
__device__ __align__(16) float g_y0[BB * PWD];
__device__ __align__(16) float g_x [BB * PGD];
__device__ __align__(16) float g_y [BB * PWD];
__device__ __align__(16) float g_Gg[BB * 4 * HGD];
__device__ __align__(16) float g_Gw[BB * 4 * HWD];
__device__ __align__(16) float g_hg[NL * 2 * BB * HGD];      // [layer][parity][b*H]
__device__ __align__(16) float g_cg[NL * BB * HGD];
__device__ __align__(16) float g_hw[NL * 2 * BB * HWD];
__device__ __align__(16) float g_cw[NL * BB * HWD];
__device__ __align__(16) float g_pg[BB * DOF];
__device__ __align__(16) float g_pw[BB * WSZ];

__device__ __forceinline__ float sigf(float x) { return 1.f / (1.f + expf(-x)); }

// ---- packed f32x2 FMA (Blackwell FFMA2; per-lane fused RN, exact vs FFMA) ---
__device__ __forceinline__ ull pack2(float lo, float hi) {
    ull r; asm("mov.b64 %0, {%1, %2};" : "=l"(r) : "f"(lo), "f"(hi)); return r;
}
__device__ __forceinline__ float2 unpack2(ull v) {
    float lo, hi; asm("mov.b64 {%0, %1}, %2;" : "=f"(lo), "=f"(hi) : "l"(v));
    float2 f; f.x = lo; f.y = hi; return f;
}
__device__ __forceinline__ void ffma2(ull& d, ull a, ull b) {
    asm("fma.rn.f32x2 %0, %1, %2, %3;" : "=l"(d) : "l"(a), "l"(b), "l"(d));
}

// ---------------- init: zero states, seed pg/pw, write t=0 outputs -----------
__global__ void init_kernel(const float* __restrict__ goal0,
                            const float* __restrict__ w0,
                            float* __restrict__ out)
{
    int tid0 = blockIdx.x * blockDim.x + threadIdx.x;
    int stride = gridDim.x * blockDim.x;
    for (int i = tid0; i < NL * BB * HGD; i += stride) {
        int l = i / (BB * HGD); int r = i % (BB * HGD);
        g_hg[(l * 2 + 0) * BB * HGD + r] = 0.f;
        g_cg[i] = 0.f;
    }
    for (int i = tid0; i < NL * BB * HWD; i += stride) {
        int l = i / (BB * HWD); int r = i % (BB * HWD);
        g_hw[(l * 2 + 0) * BB * HWD + r] = 0.f;
        g_cw[i] = 0.f;
    }
    for (int i = tid0; i < BB * DOF; i += stride) {
        float v = goal0[i];
        g_pg[i] = v;
        int b = i / DOF, d = i % DOF;
        out[b * (MS * DOF) + d] = v;                      // goals[:,0,:]
    }
    for (int i = tid0; i < BB * WSZ; i += stride) {
        float v = w0[i];
        g_pw[i] = v;
        int b = i / WSZ, c = i % WSZ;
        out[BB * MS * DOF + b * (MS * WSZ) + c] = v;      // ws[:,0,:]
    }
}

// ---------------- Ag[b][o][j] = sum_i ctx[b,i] * bgW[o,i,j] ------------------
__global__ void pre_ag_kernel(const float* __restrict__ ctx,
                              const float* __restrict__ bgW)
{
    __shared__ float Ws[CTXD][DOF];  // 12KB
    int o = blockIdx.x;
    const float* Wo = bgW + (size_t)o * CTXD * DOF;
    for (int idx = threadIdx.x; idx < CTXD * DOF; idx += blockDim.x)
        Ws[idx / DOF][idx % DOF] = Wo[idx];
    __syncthreads();
    int b = threadIdx.x;  // blockDim.x == 256
    float acc[DOF] = {0.f, 0.f, 0.f, 0.f, 0.f, 0.f};
    const float* cr = ctx + (size_t)b * CTXD;
    for (int i = 0; i < CTXD; i++) {
        float c = cr[i];
#pragma unroll
        for (int j = 0; j < DOF; j++) acc[j] += c * Ws[i][j];
    }
    float* dst = g_Ag + ((size_t)b * PGD + o) * DOF;
#pragma unroll
    for (int j = 0; j < DOF; j++) dst[j] = acc[j];
}

// ---------------- Aw[o][b][j] = sum_i ctx[b,i] * bwW[o,i,j] ------------------
// Batched GEMM: C_o(256x306) = ctx(256x512) @ W_o(512x306). FFMA2 + dbl-buffer.
__global__ void pre_aw_kernel(const float* __restrict__ ctx,
                              const float* __restrict__ bwW)
{
    int o  = blockIdx.z;
    int bm = blockIdx.x * 64;   // b tile
    int bn = blockIdx.y * 64;   // j tile
    const float* Wo = bwW + (size_t)o * CTXD * ZD;

    __shared__ float As[2][16][68];
    __shared__ float Bs[2][16][68];
    ull acc2[4][2] = {};
    int tid = threadIdx.x;
    int tx = tid % 16, ty = tid / 16;
    int sm_m  = tid >> 2;
    int sm_kq = (tid & 3) * 4;

    const int NT = CTXD / 16;
    // preload tile 0
    {
        float4 v = *(const float4*)(ctx + (size_t)(bm + sm_m) * CTXD + sm_kq);
        As[0][sm_kq + 0][sm_m] = v.x; As[0][sm_kq + 1][sm_m] = v.y;
        As[0][sm_kq + 2][sm_m] = v.z; As[0][sm_kq + 3][sm_m] = v.w;
#pragma unroll
        for (int q = 0; q < 4; q++) {
            int idx = tid + q * 256;
            int k = idx >> 6, n = idx & 63;
            int j = bn + n;
            Bs[0][k][n] = (j < ZD) ? Wo[(size_t)k * ZD + j] : 0.f;
        }
    }
    __syncthreads();

    for (int kt = 0; kt < NT; kt++) {
        int cur = kt & 1, nxt = cur ^ 1;
        bool have = (kt + 1 < NT);
        float4 va; float rb[4];
        if (have) {
            int k0 = (kt + 1) * 16;
            va = *(const float4*)(ctx + (size_t)(bm + sm_m) * CTXD + k0 + sm_kq);
#pragma unroll
            for (int q = 0; q < 4; q++) {
                int idx = tid + q * 256;
                int k = idx >> 6, n = idx & 63;
                int j = bn + n;
                rb[q] = (j < ZD) ? Wo[(size_t)(k0 + k) * ZD + j] : 0.f;
            }
        }
#pragma unroll
        for (int k = 0; k < 16; k++) {
            float4 av = *(const float4*)&As[cur][k][ty * 4];
            float4 bv = *(const float4*)&Bs[cur][k][tx * 4];
            ull b01 = pack2(bv.x, bv.y);
            ull b23 = pack2(bv.z, bv.w);
            float a[4] = {av.x, av.y, av.z, av.w};
#pragma unroll
            for (int u = 0; u < 4; u++) {
                ull aa = pack2(a[u], a[u]);
                ffma2(acc2[u][0], aa, b01);
                ffma2(acc2[u][1], aa, b23);
            }
        }
        if (have) {
            As[nxt][sm_kq + 0][sm_m] = va.x; As[nxt][sm_kq + 1][sm_m] = va.y;
            As[nxt][sm_kq + 2][sm_m] = va.z; As[nxt][sm_kq + 3][sm_m] = va.w;
#pragma unroll
            for (int q = 0; q < 4; q++) {
                int idx = tid + q * 256;
                int k = idx >> 6, n = idx & 63;
                Bs[nxt][k][n] = rb[q];
            }
        }
        __syncthreads();
    }

    // epilogue: write fp32 Aw[o][b][j] with padded row stride; zero the pad
    float* base = g_Aw + (size_t)o * BB * ZDP;
#pragma unroll
    for (int u = 0; u < 4; u++) {
        int m = bm + ty * 4 + u;
        float2 p0 = unpack2(acc2[u][0]);
        float2 p1 = unpack2(acc2[u][1]);
        float r[4] = {p0.x, p0.y, p1.x, p1.y};
#pragma unroll
        for (int v = 0; v < 4; v++) {
            int j = bn + tx * 4 + v;
            if (j < ZDP) base[(size_t)m * ZDP + j] = (j < ZD) ? r[v] : 0.f;
        }
    }
}

// ---------------- per-step bilinears: x0 (Ag·pg), y0 (Aw·z) ------------------
__global__ void bilinear_kernel(const float* __restrict__ bg_b,
                                const float* __restrict__ bw_b)
{
    if (blockIdx.x < 2048) {
        int b  = blockIdx.x >> 3;
        int og = (blockIdx.x & 7) * 64;
        __shared__ __align__(16) float zs[ZDP + 4];
        int tid = threadIdx.x;
        for (int i = tid; i < ZDP + 4; i += 256) {
            float v = 0.f;
            if (i < DOF)      v = g_pg[b * DOF + i];
            else if (i < ZD)  v = g_pw[b * WSZ + (i - DOF)];
            zs[i] = v;  // pad [306..311] = 0
        }
        __syncthreads();
        int warp = tid >> 5, lane = tid & 31;
        const float4* zs4 = (const float4*)zs;
#pragma unroll
        for (int q = 0; q < 8; q++) {
            int o = og + warp * 8 + q;
            const float4* row4 = (const float4*)(g_Aw + ((size_t)o * BB + b) * ZDP);
            float acc = 0.f;
#pragma unroll 3
            for (int j4 = lane; j4 < ZDP / 4; j4 += 32) {   // 77 float4s
                float4 f = row4[j4];
                float4 z = zs4[j4];
                acc += f.x * z.x + f.y * z.y + f.z * z.z + f.w * z.w;
            }
#pragma unroll
            for (int off = 16; off > 0; off >>= 1)
                acc += __shfl_down_sync(0xffffffffu, acc, off);
            if (lane == 0) g_y0[b * PWD + o] = acc + bw_b[o];
        }
    } else {
        int b = blockIdx.x - 2048;
        __shared__ float ps[8];
        if (threadIdx.x < DOF) ps[threadIdx.x] = g_pg[b * DOF + threadIdx.x];
        __syncthreads();
        int o = threadIdx.x;  // 256 threads
        const float* ar = g_Ag + ((size_t)b * PGD + o) * DOF;
        float acc = bg_b[o];
#pragma unroll
        for (int j = 0; j < DOF; j++) acc += ar[j] * ps[j];
        g_x0[b * PGD + o] = acc;
    }
}

// ---------------- generic dual-input GEMM: C = act(A1@W1.T + A2@W2.T + b) ----
// FFMA2 inner product + double-buffered staging (1 sync per k-tile).
struct GemmJob {
    const float* A1; const float* W1;
    const float* A2; const float* W2;
    const float* b1; const float* b2;
    float* C;  float* C2;
    int K1, K2, N, ldc, ldc2, act, nbm, nbn;
};

__global__ void gemm2_kernel(GemmJob j0, GemmJob j1, int nblk0)
{
    GemmJob jb = (blockIdx.x < (unsigned)nblk0) ? j0 : j1;
    int local  = blockIdx.x - ((blockIdx.x < (unsigned)nblk0) ? 0 : nblk0);
    int bm = (local % jb.nbm) * 64;
    int bn = (local / jb.nbm) * 64;

    __shared__ float As[2][16][68];
    __shared__ float Ws[2][16][68];
    ull acc2[4][2] = {};
    int tid = threadIdx.x;
    int tx = tid % 16, ty = tid / 16;
    int sm_m  = tid >> 2;        // row (A) / n-row (W) this thread stages
    int sm_kq = (tid & 3) * 4;   // k quad
    int gn = bn + sm_m;          // W row this thread stages

#pragma unroll 1
    for (int pass = 0; pass < 2; pass++) {
        const float* A = pass ? jb.A2 : jb.A1;
        const float* W = pass ? jb.W2 : jb.W1;
        int K = pass ? jb.K2 : jb.K1;
        if (K == 0) continue;
        int NT = K / 16;
        // preload tile 0
        {
            float4 va = *(const float4*)(A + (size_t)(bm + sm_m) * K + sm_kq);
            float4 vw = make_float4(0.f, 0.f, 0.f, 0.f);
            if (gn < jb.N) vw = *(const float4*)(W + (size_t)gn * K + sm_kq);
            As[0][sm_kq + 0][sm_m] = va.x; As[0][sm_kq + 1][sm_m] = va.y;
            As[0][sm_kq + 2][sm_m] = va.z; As[0][sm_kq + 3][sm_m] = va.w;
            Ws[0][sm_kq + 0][sm_m] = vw.x; Ws[0][sm_kq + 1][sm_m] = vw.y;
            Ws[0][sm_kq + 2][sm_m] = vw.z; Ws[0][sm_kq + 3][sm_m] = vw.w;
        }
        __syncthreads();

        for (int kt = 0; kt < NT; kt++) {
            int cur = kt & 1, nxt = cur ^ 1;
            bool have = (kt + 1 < NT);
            float4 va, vw;
            if (have) {
                int k0 = (kt + 1) * 16;
                va = *(const float4*)(A + (size_t)(bm + sm_m) * K + k0 + sm_kq);
                vw = make_float4(0.f, 0.f, 0.f, 0.f);
                if (gn < jb.N) vw = *(const float4*)(W + (size_t)gn * K + k0 + sm_kq);
            }
#pragma unroll
            for (int k = 0; k < 16; k++) {
                float4 av = *(const float4*)&As[cur][k][ty * 4];
                float4 bv = *(const float4*)&Ws[cur][k][tx * 4];
                ull b01 = pack2(bv.x, bv.y);
                ull b23 = pack2(bv.z, bv.w);
                float a[4] = {av.x, av.y, av.z, av.w};
#pragma unroll
                for (int u = 0; u < 4; u++) {
                    ull aa = pack2(a[u], a[u]);
                    ffma2(acc2[u][0], aa, b01);
                    ffma2(acc2[u][1], aa, b23);
                }
            }
            if (have) {
                As[nxt][sm_kq + 0][sm_m] = va.x; As[nxt][sm_kq + 1][sm_m] = va.y;
                As[nxt][sm_kq + 2][sm_m] = va.z; As[nxt][sm_kq + 3][sm_m] = va.w;
                Ws[nxt][sm_kq + 0][sm_m] = vw.x; Ws[nxt][sm_kq + 1][sm_m] = vw.y;
                Ws[nxt][sm_kq + 2][sm_m] = vw.z; Ws[nxt][sm_kq + 3][sm_m] = vw.w;
            }
            __syncthreads();
        }
    }
#pragma unroll
    for (int u = 0; u < 4; u++) {
        int m = bm + ty * 4 + u;
        float2 p0 = unpack2(acc2[u][0]);
        float2 p1 = unpack2(acc2[u][1]);
        float r[4] = {p0.x, p0.y, p1.x, p1.y};
#pragma unroll
        for (int v = 0; v < 4; v++) {
            int n = bn + tx * 4 + v;
            if (n < jb.N) {
                float xv = r[v];
                if (jb.b1) xv += jb.b1[n];
                if (jb.b2) xv += jb.b2[n];
                if (jb.act == 1) xv = tanhf(xv);
                jb.C[(size_t)m * jb.ldc + n] = xv;
                if (jb.C2) jb.C2[(size_t)m * jb.ldc2 + n] = xv;
            }
        }
    }
}

// ---------------- LSTM gate elementwise (both nets, one layer) ---------------
__global__ void gates_kernel(const float* __restrict__ Gg, float* __restrict__ cg,
                             float* __restrict__ hg_out,
                             const float* __restrict__ Gw, float* __restrict__ cw,
                             float* __restrict__ hw_out)
{
    const int total_g = BB * HGD;
    const int total_w = BB * HWD;
    int idx = blockIdx.x * blockDim.x + threadIdx.x;
    int stride = gridDim.x * blockDim.x;
    for (int i = idx; i < total_g + total_w; i += stride) {
        const float* G; float* c; float* h; int H; int local;
        if (i < total_g) { G = Gg; c = cg; h = hg_out; H = HGD; local = i; }
        else             { G = Gw; c = cw; h = hw_out; H = HWD; local = i - total_g; }
        int b = local / H, o = local % H;
        const float* gr = G + (size_t)b * 4 * H;
        float gi = gr[o];
        float gf = gr[H + o];
        float gc = gr[2 * H + o];
        float go = gr[3 * H + o];
        float cn = sigf(gf) * c[local] + sigf(gi) * tanhf(gc);
        c[local] = cn;
        h[local] = sigf(go) * tanhf(cn);
    }
}

// ---------------- host ------------------------------------------------------
static GemmJob mk(const float* A1, const float* W1, int K1,
                  const float* A2, const float* W2, int K2,
                  const float* b1, const float* b2,
                  float* C, int N, int ldc, int act,
                  float* C2 = nullptr, int ldc2 = 0)
{
    GemmJob j;
    j.A1 = A1; j.W1 = W1; j.A2 = A2; j.W2 = W2; j.b1 = b1; j.b2 = b2;
    j.C = C; j.C2 = C2;
    j.K1 = K1; j.K2 = K2; j.N = N; j.ldc = ldc; j.ldc2 = ldc2; j.act = act;
    j.nbm = BB / 64; j.nbn = (N + 63) / 64;
    return j;
}

extern "C" void kernel_launch(void* const* d_in, const int* in_sizes, int n_in,
                              void* d_out, int out_size)
{
    const float* ctx    = (const float*)d_in[0];
    const float* goal0  = (const float*)d_in[1];
    const float* w0     = (const float*)d_in[2];
    const float* bg_W   = (const float*)d_in[3];
    const float* bg_b   = (const float*)d_in[4];
    const float* bw_W   = (const float*)d_in[5];
    const float* bw_b   = (const float*)d_in[6];
    const float* fcg_W  = (const float*)d_in[7];
    const float* fcg_b  = (const float*)d_in[8];
    const float* fcw_W  = (const float*)d_in[9];
    const float* fcw_b  = (const float*)d_in[10];
    const float* lg_Wih = (const float*)d_in[11];
    const float* lg_Whh = (const float*)d_in[12];
    const float* lg_bih = (const float*)d_in[13];
    const float* lg_bhh = (const float*)d_in[14];
    const float* lw_Wih = (const float*)d_in[15];
    const float* lw_Whh = (const float*)d_in[16];
    const float* lw_bih = (const float*)d_in[17];
    const float* lw_bhh = (const float*)d_in[18];
    const float* og_W   = (const float*)d_in[19];
    const float* og_b   = (const float*)d_in[20];
    const float* ow_W   = (const float*)d_in[21];
    const float* ow_b   = (const float*)d_in[22];

    float* out   = (float*)d_out;
    float* out_w = out + BB * MS * DOF;

    // scratch addresses
    float *x0, *y0, *x, *y, *Gg, *Gw, *hg, *cg, *hw, *cw, *pgp, *pwp;
    cudaGetSymbolAddress((void**)&x0,  g_x0);
    cudaGetSymbolAddress((void**)&y0,  g_y0);
    cudaGetSymbolAddress((void**)&x,   g_x);
    cudaGetSymbolAddress((void**)&y,   g_y);
    cudaGetSymbolAddress((void**)&Gg,  g_Gg);
    cudaGetSymbolAddress((void**)&Gw,  g_Gw);
    cudaGetSymbolAddress((void**)&hg,  g_hg);
    cudaGetSymbolAddress((void**)&cg,  g_cg);
    cudaGetSymbolAddress((void**)&hw,  g_hw);
    cudaGetSymbolAddress((void**)&cw,  g_cw);
    cudaGetSymbolAddress((void**)&pgp, g_pg);
    cudaGetSymbolAddress((void**)&pwp, g_pw);

    init_kernel<<<512, 256>>>(goal0, w0, out);
    pre_ag_kernel<<<PGD, 256>>>(ctx, bg_W);
    {
        dim3 g(4, 5, PWD);
        pre_aw_kernel<<<g, 256>>>(ctx, bw_W);
    }

    const int szG = BB * HGD;   // per (layer,parity) slab for g-net
    const int szW = BB * HWD;

    for (int t = 0; t < NSTEP; t++) {
        int p = t & 1;

        bilinear_kernel<<<2304, 256>>>(bg_b, bw_b);

        // FC layers (tanh)
        {
            GemmJob a = mk(x0, fcg_W, PGD, nullptr, nullptr, 0, fcg_b, nullptr, x, PGD, PGD, 1);
            GemmJob b = mk(y0, fcw_W, PWD, nullptr, nullptr, 0, fcw_b, nullptr, y, PWD, PWD, 1);
            int n0 = a.nbm * a.nbn;
            gemm2_kernel<<<n0 + b.nbm * b.nbn, 256>>>(a, b, n0);
        }
        // LSTM layer 0 pre-activations
        {
            GemmJob a = mk(x, lg_Wih, PGD, hg + (0 * 2 + p) * szG, lg_Whh, HGD,
                           lg_bih, lg_bhh, Gg, 4 * HGD, 4 * HGD, 0);
            GemmJob b = mk(y, lw_Wih, PWD, hw + (0 * 2 + p) * szW, lw_Whh, HWD,
                           lw_bih, lw_bhh, Gw, 4 * HWD, 4 * HWD, 0);
            int n0 = a.nbm * a.nbn;
            gemm2_kernel<<<n0 + b.nbm * b.nbn, 256>>>(a, b, n0);
        }
        gates_kernel<<<768, 256>>>(Gg, cg + 0 * szG, hg + (0 * 2 + (1 - p)) * szG,
                                   Gw, cw + 0 * szW, hw + (0 * 2 + (1 - p)) * szW);
        // LSTM layer 1 pre-activations
        {
            GemmJob a = mk(hg + (0 * 2 + (1 - p)) * szG, lg_Wih + 4 * HGD * PGD, HGD,
                           hg + (1 * 2 + p) * szG, lg_Whh + 4 * HGD * HGD, HGD,
                           lg_bih + 4 * HGD, lg_bhh + 4 * HGD, Gg, 4 * HGD, 4 * HGD, 0);
            GemmJob b = mk(hw + (0 * 2 + (1 - p)) * szW, lw_Wih + 4 * HWD * PWD, HWD,
                           hw + (1 * 2 + p) * szW, lw_Whh + 4 * HWD * HWD, HWD,
                           lw_bih + 4 * HWD, lw_bhh + 4 * HWD, Gw, 4 * HWD, 4 * HWD, 0);
            int n0 = a.nbm * a.nbn;
            gemm2_kernel<<<n0 + b.nbm * b.nbn, 256>>>(a, b, n0);
        }
        gates_kernel<<<768, 256>>>(Gg, cg + 1 * szG, hg + (1 * 2 + (1 - p)) * szG,
                                   Gw, cw + 1 * szW, hw + (1 * 2 + (1 - p)) * szW);
        // output heads: also write into d_out slices and pg/pw state
        {
            GemmJob a = mk(hw + (1 * 2 + (1 - p)) * szW, ow_W, HWD, nullptr, nullptr, 0,
                           ow_b, nullptr, pwp, WSZ, WSZ, 0,
                           out_w + (t + 1) * WSZ, MS * WSZ);
            GemmJob b = mk(hg + (1 * 2 + (1 - p)) * szG, og_W, HGD, nullptr, nullptr, 0,
                           og_b, nullptr, pgp, DOF, DOF, 0,
                           out + (t + 1) * DOF, MS * DOF);
            int n0 = a.nbm * a.nbn;
            gemm2_kernel<<<n0 + b.nbm * b.nbn, 256>>>(a, b, n0);
        }
    }
}

// round 17
// speedup vs baseline: 1.0582x; 1.0582x over previous
#include <cuda_runtime.h>
#include <cstdint>
#include <math.h>

// Problem constants (fixed by setup_inputs)
#define BB   256   // batch
#define CTXD 512
#define DOF  6
#define WSZ  300
#define ZD   306   // DOF + WSZ
#define ZDP  308   // padded row stride for g_Aw (16B-aligned rows)
#define PGD  256
#define PWD  512
#define HGD  256
#define HWD  512
#define NL   2
#define MS   20
#define NSTEP (MS - 1)

typedef unsigned long long ull;

// ---------------- scratch (device globals; no runtime allocation) ------------
__device__ __align__(16) float g_Aw[(size_t)PWD * BB * ZDP]; // [o][b][j] pad308 (~161MB)
__device__ __align__(16) float g_Ag[BB * PGD * DOF];         // [b][o][j]
__device__ __align__(16) float g_x0[BB * PGD];
__device__ __align__(16) float g_y0[BB * PWD];
__device__ __align__(16) float g_x [BB * PGD];
__device__ __align__(16) float g_y [BB * PWD];
__device__ __align__(16) float g_Gg[BB * 4 * HGD];
__device__ __align__(16) float g_Gw[BB * 4 * HWD];
__device__ __align__(16) float g_hg[NL * 2 * BB * HGD];      // [layer][parity][b*H]
__device__ __align__(16) float g_cg[NL * BB * HGD];
__device__ __align__(16) float g_hw[NL * 2 * BB * HWD];
__device__ __align__(16) float g_cw[NL * BB * HWD];
__device__ __align__(16) float g_pg[BB * DOF];
__device__ __align__(16) float g_pw[BB * WSZ];

__device__ __forceinline__ float sigf(float x) { return 1.f / (1.f + expf(-x)); }

// ---- packed f32x2 FMA (Blackwell FFMA2; per-lane fused RN, exact vs FFMA) ---
__device__ __forceinline__ ull pack2(float lo, float hi) {
    ull r; asm("mov.b64 %0, {%1, %2};" : "=l"(r) : "f"(lo), "f"(hi)); return r;
}
__device__ __forceinline__ float2 unpack2(ull v) {
    float lo, hi; asm("mov.b64 {%0, %1}, %2;" : "=f"(lo), "=f"(hi) : "l"(v));
    float2 f; f.x = lo; f.y = hi; return f;
}
__device__ __forceinline__ void ffma2(ull& d, ull a, ull b) {
    asm("fma.rn.f32x2 %0, %1, %2, %3;" : "=l"(d) : "l"(a), "l"(b), "l"(d));
}

// ---------------- init: zero states, seed pg/pw, write t=0 outputs -----------
__global__ void init_kernel(const float* __restrict__ goal0,
                            const float* __restrict__ w0,
                            float* __restrict__ out)
{
    int tid0 = blockIdx.x * blockDim.x + threadIdx.x;
    int stride = gridDim.x * blockDim.x;
    for (int i = tid0; i < NL * BB * HGD; i += stride) {
        int l = i / (BB * HGD); int r = i % (BB * HGD);
        g_hg[(l * 2 + 0) * BB * HGD + r] = 0.f;
        g_cg[i] = 0.f;
    }
    for (int i = tid0; i < NL * BB * HWD; i += stride) {
        int l = i / (BB * HWD); int r = i % (BB * HWD);
        g_hw[(l * 2 + 0) * BB * HWD + r] = 0.f;
        g_cw[i] = 0.f;
    }
    for (int i = tid0; i < BB * DOF; i += stride) {
        float v = goal0[i];
        g_pg[i] = v;
        int b = i / DOF, d = i % DOF;
        out[b * (MS * DOF) + d] = v;                      // goals[:,0,:]
    }
    for (int i = tid0; i < BB * WSZ; i += stride) {
        float v = w0[i];
        g_pw[i] = v;
        int b = i / WSZ, c = i % WSZ;
        out[BB * MS * DOF + b * (MS * WSZ) + c] = v;      // ws[:,0,:]
    }
}

// ---------------- Ag[b][o][j] = sum_i ctx[b,i] * bgW[o,i,j] ------------------
__global__ void pre_ag_kernel(const float* __restrict__ ctx,
                              const float* __restrict__ bgW)
{
    __shared__ float Ws[CTXD][DOF];  // 12KB
    int o = blockIdx.x;
    const float* Wo = bgW + (size_t)o * CTXD * DOF;
    for (int idx = threadIdx.x; idx < CTXD * DOF; idx += blockDim.x)
        Ws[idx / DOF][idx % DOF] = Wo[idx];
    __syncthreads();
    int b = threadIdx.x;  // blockDim.x == 256
    float acc[DOF] = {0.f, 0.f, 0.f, 0.f, 0.f, 0.f};
    const float* cr = ctx + (size_t)b * CTXD;
    for (int i = 0; i < CTXD; i++) {
        float c = cr[i];
#pragma unroll
        for (int j = 0; j < DOF; j++) acc[j] += c * Ws[i][j];
    }
    float* dst = g_Ag + ((size_t)b * PGD + o) * DOF;
#pragma unroll
    for (int j = 0; j < DOF; j++) dst[j] = acc[j];
}

// ---------------- Aw[o][b][j] = sum_i ctx[b,i] * bwW[o,i,j] ------------------
// Batched GEMM: C_o(256x306) = ctx(256x512) @ W_o(512x306). FFMA2 + dbl-buffer.
__global__ void pre_aw_kernel(const float* __restrict__ ctx,
                              const float* __restrict__ bwW)
{
    int o  = blockIdx.z;
    int bm = blockIdx.x * 64;   // b tile
    int bn = blockIdx.y * 64;   // j tile
    const float* Wo = bwW + (size_t)o * CTXD * ZD;

    __shared__ float As[2][16][68];
    __shared__ float Bs[2][16][68];
    ull acc2[4][2] = {};
    int tid = threadIdx.x;
    int tx = tid % 16, ty = tid / 16;
    int sm_m  = tid >> 2;
    int sm_kq = (tid & 3) * 4;

    const int NT = CTXD / 16;
    // preload tile 0
    {
        float4 v = *(const float4*)(ctx + (size_t)(bm + sm_m) * CTXD + sm_kq);
        As[0][sm_kq + 0][sm_m] = v.x; As[0][sm_kq + 1][sm_m] = v.y;
        As[0][sm_kq + 2][sm_m] = v.z; As[0][sm_kq + 3][sm_m] = v.w;
#pragma unroll
        for (int q = 0; q < 4; q++) {
            int idx = tid + q * 256;
            int k = idx >> 6, n = idx & 63;
            int j = bn + n;
            Bs[0][k][n] = (j < ZD) ? Wo[(size_t)k * ZD + j] : 0.f;
        }
    }
    __syncthreads();

    for (int kt = 0; kt < NT; kt++) {
        int cur = kt & 1, nxt = cur ^ 1;
        bool have = (kt + 1 < NT);
        float4 va; float rb[4];
        if (have) {
            int k0 = (kt + 1) * 16;
            va = *(const float4*)(ctx + (size_t)(bm + sm_m) * CTXD + k0 + sm_kq);
#pragma unroll
            for (int q = 0; q < 4; q++) {
                int idx = tid + q * 256;
                int k = idx >> 6, n = idx & 63;
                int j = bn + n;
                rb[q] = (j < ZD) ? Wo[(size_t)(k0 + k) * ZD + j] : 0.f;
            }
        }
#pragma unroll
        for (int k = 0; k < 16; k++) {
            float4 av = *(const float4*)&As[cur][k][ty * 4];
            float4 bv = *(const float4*)&Bs[cur][k][tx * 4];
            ull b01 = pack2(bv.x, bv.y);
            ull b23 = pack2(bv.z, bv.w);
            float a[4] = {av.x, av.y, av.z, av.w};
#pragma unroll
            for (int u = 0; u < 4; u++) {
                ull aa = pack2(a[u], a[u]);
                ffma2(acc2[u][0], aa, b01);
                ffma2(acc2[u][1], aa, b23);
            }
        }
        if (have) {
            As[nxt][sm_kq + 0][sm_m] = va.x; As[nxt][sm_kq + 1][sm_m] = va.y;
            As[nxt][sm_kq + 2][sm_m] = va.z; As[nxt][sm_kq + 3][sm_m] = va.w;
#pragma unroll
            for (int q = 0; q < 4; q++) {
                int idx = tid + q * 256;
                int k = idx >> 6, n = idx & 63;
                Bs[nxt][k][n] = rb[q];
            }
        }
        __syncthreads();
    }

    // epilogue: write fp32 Aw[o][b][j] with padded row stride; zero the pad
    float* base = g_Aw + (size_t)o * BB * ZDP;
#pragma unroll
    for (int u = 0; u < 4; u++) {
        int m = bm + ty * 4 + u;
        float2 p0 = unpack2(acc2[u][0]);
        float2 p1 = unpack2(acc2[u][1]);
        float r[4] = {p0.x, p0.y, p1.x, p1.y};
#pragma unroll
        for (int v = 0; v < 4; v++) {
            int j = bn + tx * 4 + v;
            if (j < ZDP) base[(size_t)m * ZDP + j] = (j < ZD) ? r[v] : 0.f;
        }
    }
}

// ---------------- per-step bilinears: x0 (Ag·pg), y0 (Aw·z) ------------------
// Scalar-load form (measured 31.5us, DRAM 66%); reads padded-stride Aw rows.
__global__ void bilinear_kernel(const float* __restrict__ bg_b,
                                const float* __restrict__ bw_b)
{
    if (blockIdx.x < 2048) {
        int b  = blockIdx.x >> 3;
        int og = (blockIdx.x & 7) * 64;
        __shared__ float zs[320];
        int tid = threadIdx.x;
        for (int i = tid; i < 320; i += 256) {
            float v = 0.f;
            if (i < DOF)      v = g_pg[b * DOF + i];
            else if (i < ZD)  v = g_pw[b * WSZ + (i - DOF)];
            zs[i] = v;
        }
        __syncthreads();
        int warp = tid >> 5, lane = tid & 31;
#pragma unroll
        for (int q = 0; q < 8; q++) {
            int o = og + warp * 8 + q;
            const float* row = g_Aw + ((size_t)o * BB + b) * ZDP;
            float acc = 0.f;
            for (int j = lane; j < ZD; j += 32) acc += row[j] * zs[j];
#pragma unroll
            for (int off = 16; off > 0; off >>= 1)
                acc += __shfl_down_sync(0xffffffffu, acc, off);
            if (lane == 0) g_y0[b * PWD + o] = acc + bw_b[o];
        }
    } else {
        int b = blockIdx.x - 2048;
        __shared__ float ps[8];
        if (threadIdx.x < DOF) ps[threadIdx.x] = g_pg[b * DOF + threadIdx.x];
        __syncthreads();
        int o = threadIdx.x;  // 256 threads
        const float* ar = g_Ag + ((size_t)b * PGD + o) * DOF;
        float acc = bg_b[o];
#pragma unroll
        for (int j = 0; j < DOF; j++) acc += ar[j] * ps[j];
        g_x0[b * PGD + o] = acc;
    }
}

// ---------------- generic dual-input GEMM: C = act(A1@W1.T + A2@W2.T + b) ----
// FFMA2 inner product + double-buffered staging (1 sync per k-tile).
struct GemmJob {
    const float* A1; const float* W1;
    const float* A2; const float* W2;
    const float* b1; const float* b2;
    float* C;  float* C2;
    int K1, K2, N, ldc, ldc2, act, nbm, nbn;
};

__global__ void gemm2_kernel(GemmJob j0, GemmJob j1, int nblk0)
{
    GemmJob jb = (blockIdx.x < (unsigned)nblk0) ? j0 : j1;
    int local  = blockIdx.x - ((blockIdx.x < (unsigned)nblk0) ? 0 : nblk0);
    int bm = (local % jb.nbm) * 64;
    int bn = (local / jb.nbm) * 64;

    __shared__ float As[2][16][68];
    __shared__ float Ws[2][16][68];
    ull acc2[4][2] = {};
    int tid = threadIdx.x;
    int tx = tid % 16, ty = tid / 16;
    int sm_m  = tid >> 2;        // row (A) / n-row (W) this thread stages
    int sm_kq = (tid & 3) * 4;   // k quad
    int gn = bn + sm_m;          // W row this thread stages

#pragma unroll 1
    for (int pass = 0; pass < 2; pass++) {
        const float* A = pass ? jb.A2 : jb.A1;
        const float* W = pass ? jb.W2 : jb.W1;
        int K = pass ? jb.K2 : jb.K1;
        if (K == 0) continue;
        int NT = K / 16;
        // preload tile 0
        {
            float4 va = *(const float4*)(A + (size_t)(bm + sm_m) * K + sm_kq);
            float4 vw = make_float4(0.f, 0.f, 0.f, 0.f);
            if (gn < jb.N) vw = *(const float4*)(W + (size_t)gn * K + sm_kq);
            As[0][sm_kq + 0][sm_m] = va.x; As[0][sm_kq + 1][sm_m] = va.y;
            As[0][sm_kq + 2][sm_m] = va.z; As[0][sm_kq + 3][sm_m] = va.w;
            Ws[0][sm_kq + 0][sm_m] = vw.x; Ws[0][sm_kq + 1][sm_m] = vw.y;
            Ws[0][sm_kq + 2][sm_m] = vw.z; Ws[0][sm_kq + 3][sm_m] = vw.w;
        }
        __syncthreads();

        for (int kt = 0; kt < NT; kt++) {
            int cur = kt & 1, nxt = cur ^ 1;
            bool have = (kt + 1 < NT);
            float4 va, vw;
            if (have) {
                int k0 = (kt + 1) * 16;
                va = *(const float4*)(A + (size_t)(bm + sm_m) * K + k0 + sm_kq);
                vw = make_float4(0.f, 0.f, 0.f, 0.f);
                if (gn < jb.N) vw = *(const float4*)(W + (size_t)gn * K + k0 + sm_kq);
            }
#pragma unroll
            for (int k = 0; k < 16; k++) {
                float4 av = *(const float4*)&As[cur][k][ty * 4];
                float4 bv = *(const float4*)&Ws[cur][k][tx * 4];
                ull b01 = pack2(bv.x, bv.y);
                ull b23 = pack2(bv.z, bv.w);
                float a[4] = {av.x, av.y, av.z, av.w};
#pragma unroll
                for (int u = 0; u < 4; u++) {
                    ull aa = pack2(a[u], a[u]);
                    ffma2(acc2[u][0], aa, b01);
                    ffma2(acc2[u][1], aa, b23);
                }
            }
            if (have) {
                As[nxt][sm_kq + 0][sm_m] = va.x; As[nxt][sm_kq + 1][sm_m] = va.y;
                As[nxt][sm_kq + 2][sm_m] = va.z; As[nxt][sm_kq + 3][sm_m] = va.w;
                Ws[nxt][sm_kq + 0][sm_m] = vw.x; Ws[nxt][sm_kq + 1][sm_m] = vw.y;
                Ws[nxt][sm_kq + 2][sm_m] = vw.z; Ws[nxt][sm_kq + 3][sm_m] = vw.w;
            }
            __syncthreads();
        }
    }
#pragma unroll
    for (int u = 0; u < 4; u++) {
        int m = bm + ty * 4 + u;
        float2 p0 = unpack2(acc2[u][0]);
        float2 p1 = unpack2(acc2[u][1]);
        float r[4] = {p0.x, p0.y, p1.x, p1.y};
#pragma unroll
        for (int v = 0; v < 4; v++) {
            int n = bn + tx * 4 + v;
            if (n < jb.N) {
                float xv = r[v];
                if (jb.b1) xv += jb.b1[n];
                if (jb.b2) xv += jb.b2[n];
                if (jb.act == 1) xv = tanhf(xv);
                jb.C[(size_t)m * jb.ldc + n] = xv;
                if (jb.C2) jb.C2[(size_t)m * jb.ldc2 + n] = xv;
            }
        }
    }
}

// ---------------- LSTM gate elementwise (both nets, one layer) ---------------
__global__ void gates_kernel(const float* __restrict__ Gg, float* __restrict__ cg,
                             float* __restrict__ hg_out,
                             const float* __restrict__ Gw, float* __restrict__ cw,
                             float* __restrict__ hw_out)
{
    const int total_g = BB * HGD;
    const int total_w = BB * HWD;
    int idx = blockIdx.x * blockDim.x + threadIdx.x;
    int stride = gridDim.x * blockDim.x;
    for (int i = idx; i < total_g + total_w; i += stride) {
        const float* G; float* c; float* h; int H; int local;
        if (i < total_g) { G = Gg; c = cg; h = hg_out; H = HGD; local = i; }
        else             { G = Gw; c = cw; h = hw_out; H = HWD; local = i - total_g; }
        int b = local / H, o = local % H;
        const float* gr = G + (size_t)b * 4 * H;
        float gi = gr[o];
        float gf = gr[H + o];
        float gc = gr[2 * H + o];
        float go = gr[3 * H + o];
        float cn = sigf(gf) * c[local] + sigf(gi) * tanhf(gc);
        c[local] = cn;
        h[local] = sigf(go) * tanhf(cn);
    }
}

// ---------------- host ------------------------------------------------------
static GemmJob mk(const float* A1, const float* W1, int K1,
                  const float* A2, const float* W2, int K2,
                  const float* b1, const float* b2,
                  float* C, int N, int ldc, int act,
                  float* C2 = nullptr, int ldc2 = 0)
{
    GemmJob j;
    j.A1 = A1; j.W1 = W1; j.A2 = A2; j.W2 = W2; j.b1 = b1; j.b2 = b2;
    j.C = C; j.C2 = C2;
    j.K1 = K1; j.K2 = K2; j.N = N; j.ldc = ldc; j.ldc2 = ldc2; j.act = act;
    j.nbm = BB / 64; j.nbn = (N + 63) / 64;
    return j;
}

extern "C" void kernel_launch(void* const* d_in, const int* in_sizes, int n_in,
                              void* d_out, int out_size)
{
    const float* ctx    = (const float*)d_in[0];
    const float* goal0  = (const float*)d_in[1];
    const float* w0     = (const float*)d_in[2];
    const float* bg_W   = (const float*)d_in[3];
    const float* bg_b   = (const float*)d_in[4];
    const float* bw_W   = (const float*)d_in[5];
    const float* bw_b   = (const float*)d_in[6];
    const float* fcg_W  = (const float*)d_in[7];
    const float* fcg_b  = (const float*)d_in[8];
    const float* fcw_W  = (const float*)d_in[9];
    const float* fcw_b  = (const float*)d_in[10];
    const float* lg_Wih = (const float*)d_in[11];
    const float* lg_Whh = (const float*)d_in[12];
    const float* lg_bih = (const float*)d_in[13];
    const float* lg_bhh = (const float*)d_in[14];
    const float* lw_Wih = (const float*)d_in[15];
    const float* lw_Whh = (const float*)d_in[16];
    const float* lw_bih = (const float*)d_in[17];
    const float* lw_bhh = (const float*)d_in[18];
    const float* og_W   = (const float*)d_in[19];
    const float* og_b   = (const float*)d_in[20];
    const float* ow_W   = (const float*)d_in[21];
    const float* ow_b   = (const float*)d_in[22];

    float* out   = (float*)d_out;
    float* out_w = out + BB * MS * DOF;

    // scratch addresses
    float *x0, *y0, *x, *y, *Gg, *Gw, *hg, *cg, *hw, *cw, *pgp, *pwp;
    cudaGetSymbolAddress((void**)&x0,  g_x0);
    cudaGetSymbolAddress((void**)&y0,  g_y0);
    cudaGetSymbolAddress((void**)&x,   g_x);
    cudaGetSymbolAddress((void**)&y,   g_y);
    cudaGetSymbolAddress((void**)&Gg,  g_Gg);
    cudaGetSymbolAddress((void**)&Gw,  g_Gw);
    cudaGetSymbolAddress((void**)&hg,  g_hg);
    cudaGetSymbolAddress((void**)&cg,  g_cg);
    cudaGetSymbolAddress((void**)&hw,  g_hw);
    cudaGetSymbolAddress((void**)&cw,  g_cw);
    cudaGetSymbolAddress((void**)&pgp, g_pg);
    cudaGetSymbolAddress((void**)&pwp, g_pw);

    init_kernel<<<512, 256>>>(goal0, w0, out);
    pre_ag_kernel<<<PGD, 256>>>(ctx, bg_W);
    {
        dim3 g(4, 5, PWD);
        pre_aw_kernel<<<g, 256>>>(ctx, bw_W);
    }

    const int szG = BB * HGD;   // per (layer,parity) slab for g-net
    const int szW = BB * HWD;

    for (int t = 0; t < NSTEP; t++) {
        int p = t & 1;

        bilinear_kernel<<<2304, 256>>>(bg_b, bw_b);

        // FC layers (tanh)
        {
            GemmJob a = mk(x0, fcg_W, PGD, nullptr, nullptr, 0, fcg_b, nullptr, x, PGD, PGD, 1);
            GemmJob b = mk(y0, fcw_W, PWD, nullptr, nullptr, 0, fcw_b, nullptr, y, PWD, PWD, 1);
            int n0 = a.nbm * a.nbn;
            gemm2_kernel<<<n0 + b.nbm * b.nbn, 256>>>(a, b, n0);
        }
        // LSTM layer 0 pre-activations
        {
            GemmJob a = mk(x, lg_Wih, PGD, hg + (0 * 2 + p) * szG, lg_Whh, HGD,
                           lg_bih, lg_bhh, Gg, 4 * HGD, 4 * HGD, 0);
            GemmJob b = mk(y, lw_Wih, PWD, hw + (0 * 2 + p) * szW, lw_Whh, HWD,
                           lw_bih, lw_bhh, Gw, 4 * HWD, 4 * HWD, 0);
            int n0 = a.nbm * a.nbn;
            gemm2_kernel<<<n0 + b.nbm * b.nbn, 256>>>(a, b, n0);
        }
        gates_kernel<<<768, 256>>>(Gg, cg + 0 * szG, hg + (0 * 2 + (1 - p)) * szG,
                                   Gw, cw + 0 * szW, hw + (0 * 2 + (1 - p)) * szW);
        // LSTM layer 1 pre-activations
        {
            GemmJob a = mk(hg + (0 * 2 + (1 - p)) * szG, lg_Wih + 4 * HGD * PGD, HGD,
                           hg + (1 * 2 + p) * szG, lg_Whh + 4 * HGD * HGD, HGD,
                           lg_bih + 4 * HGD, lg_bhh + 4 * HGD, Gg, 4 * HGD, 4 * HGD, 0);
            GemmJob b = mk(hw + (0 * 2 + (1 - p)) * szW, lw_Wih + 4 * HWD * PWD, HWD,
                           hw + (1 * 2 + p) * szW, lw_Whh + 4 * HWD * HWD, HWD,
                           lw_bih + 4 * HWD, lw_bhh + 4 * HWD, Gw, 4 * HWD, 4 * HWD, 0);
            int n0 = a.nbm * a.nbn;
            gemm2_kernel<<<n0 + b.nbm * b.nbn, 256>>>(a, b, n0);
        }
        gates_kernel<<<768, 256>>>(Gg, cg + 1 * szG, hg + (1 * 2 + (1 - p)) * szG,
                                   Gw, cw + 1 * szW, hw + (1 * 2 + (1 - p)) * szW);
        // output heads: also write into d_out slices and pg/pw state
        {
            GemmJob a = mk(hw + (1 * 2 + (1 - p)) * szW, ow_W, HWD, nullptr, nullptr, 0,
                           ow_b, nullptr, pwp, WSZ, WSZ, 0,
                           out_w + (t + 1) * WSZ, MS * WSZ);
            GemmJob b = mk(hg + (1 * 2 + (1 - p)) * szG, og_W, HGD, nullptr, nullptr, 0,
                           og_b, nullptr, pgp, DOF, DOF, 0,
                           out + (t + 1) * DOF, MS * DOF);
            int n0 = a.nbm * a.nbn;
            gemm2_kernel<<<n0 + b.nbm * b.nbn, 256>>>(a, b, n0);
        }
    }
}